// round 5
// baseline (speedup 1.0000x reference)
#include <cuda_runtime.h>
#include <cstdlib>

// Problem dims (LNCCLoss_15539191677017): [B=2, C=1, D=160, H=192, W=160] fp32
#define W_   160
#define H_   192
#define D_   160
#define NB   2
#define HW_  (H_ * W_)                 // 30720
#define NTOT (NB * D_ * HW_)           // 9830400

// Tile config
#define TX   32       // output tile x
#define TY   16       // output tile y
#define IXW  40       // inner (products/means) = out + 8
#define IYH  24
#define RXW  48       // raw load = inner + 8
#define RYH  32
#define ZC   40       // z-chunk
#define CZ   4        // chunks
#define GX   5        // 160/32
#define GY   12       // 192/16
#define NBLK (GX * GY * CZ * NB)       // 480

// Smem pitches (floats)
#define P_IN   41
#define P_OUT  33
#define P_RAW  49

// Smem layout (float offsets)
#define OFF_RXB   0                         // ring xy-boxed inputs: 2 x 10 x (24*41)
#define SZ_XB_SL  (IYH * P_IN)              // 984
#define OFF_RPXB  (OFF_RXB + 2*10*SZ_XB_SL) // ring xy-boxed products: 3 x 10 x (16*33)
#define SZ_PX_SL  (TY * P_OUT)              // 528
#define OFF_RAW   (OFF_RPXB + 3*10*SZ_PX_SL)
#define RAW_FS    (RYH * P_RAW + 1)         // 1569
#define OFF_TMP   (OFF_RAW + 2*RAW_FS)
#define TMP_FS    (RYH * P_IN + 1)          // 1313
#define TMP2_FS   (IYH * P_OUT + 1)         // 793
#define OFF_PROD  (OFF_TMP + 2*TMP_FS)
#define OFF_SZS   (OFF_PROD + 3*SZ_XB_SL)
#define SMEM_FL   (OFF_SZS + 2*SZ_XB_SL)
#define SMEM_BYTES (SMEM_FL * 4)            // 184816

__device__ float g_block[NBLK];   // per-block partial cc sums (tiny)

__device__ __forceinline__ int iclampi(int v, int lo, int hi) {
    return v < lo ? lo : (v > hi ? hi : v);
}

__global__ void __launch_bounds__(512, 1)
lncc_fused_kernel(const float* __restrict__ yt, const float* __restrict__ yp)
{
    extern __shared__ float sm[];
    const int tid = threadIdx.x;
    const int x0 = blockIdx.x * TX;
    const int y0 = blockIdx.y * TY;
    const int cz = blockIdx.z & 3;
    const int b  = blockIdx.z >> 2;
    const int z0 = cz * ZC;

    const float* __restrict__ bT = yt + (long)b * D_ * HW_;
    const float* __restrict__ bP = yp + (long)b * D_ * HW_;

    const int pLo = max(z0 - 4, 0);
    const int pHi = min(z0 + ZC + 3, D_ - 1);
    int zx = max(pLo - 4, 0);         // next raw slice to xy-box
    int next_out = z0;
    float rSn = 0.f, rSt = 0.f, rSp = 0.f;   // per-thread product z-window sums
    float acc = 0.f;
    const int aOut = (tid >> 5) * P_OUT + (tid & 31);  // oy=tid/32, ox=tid%32
    const float inv_win = 1.0f / 729.0f;
    const float eps = 1e-6f;

    for (int zp = pLo; zp <= pHi; ++zp) {
        const int need = min(zp + 4, D_ - 1);

        // ---- Stage 1: produce xy-boxed input slices into ring ----
        while (zx <= need) {
            // load raw slice zx (clamped x,y per element) into staging
            {
                const long sb = (long)zx * HW_;
                for (int i = tid; i < RXW * RYH; i += 512) {
                    int r = i / RXW, x = i - r * RXW;
                    int gx = iclampi(x0 - 8 + x, 0, W_ - 1);
                    int gy = iclampi(y0 - 8 + r, 0, H_ - 1);
                    long o = sb + (long)gy * W_ + gx;
                    sm[OFF_RAW + r * P_RAW + x]           = bT[o];
                    sm[OFF_RAW + RAW_FS + r * P_RAW + x]  = bP[o];
                }
            }
            __syncthreads();
            // x-box: rows RYH x 5 segs of 8, 2 fields -> 320 workers.
            // Valid centers exact (per-element clamped raw); halo centers
            // (gx<0 or gx>W-1) replicated from the edge value afterward.
            if (tid < 320) {
                int f = tid & 1, w = tid >> 1;
                int r = w / 5, s = w - r * 5;
                int src = OFF_RAW + f * RAW_FS + r * P_RAW + s * 8;
                int dst = OFF_TMP + f * TMP_FS + r * P_IN + s * 8;
                float S = 0.f, keep = 0.f;
                #pragma unroll
                for (int k = 0; k < 9; ++k) S += sm[src + k];
                #pragma unroll
                for (int j = 0; j < 8; ++j) {
                    sm[dst + j] = S;
                    if (s == 0 && j == 4) keep = S;   // value at gx = x0 (edge if x0==0)
                    if (s == 4 && j == 3) keep = S;   // value at gx = x0+31 (edge if x0==128)
                    if (j < 7) S += sm[src + j + 9] - sm[src + j];
                }
                if (x0 == 0 && s == 0) {
                    sm[dst+0] = keep; sm[dst+1] = keep; sm[dst+2] = keep; sm[dst+3] = keep;
                }
                if (x0 == W_ - TX && s == 4) {
                    sm[dst+4] = keep; sm[dst+5] = keep; sm[dst+6] = keep; sm[dst+7] = keep;
                }
            }
            __syncthreads();
            // y-box -> ring slot: cols IXW x 3 segs of 8, 2 fields -> 240 workers.
            // Same edge replication for halo y rows.
            {
                const int slot = zx % 10;
                if (tid < 240) {
                    int f = tid & 1, w = tid >> 1;
                    int c = w / 3, s = w - c * 3;
                    int src = OFF_TMP + f * TMP_FS + (s * 8) * P_IN + c;
                    int dst = OFF_RXB + (f * 10 + slot) * SZ_XB_SL + (s * 8) * P_IN + c;
                    float S = 0.f, keep = 0.f;
                    #pragma unroll
                    for (int k = 0; k < 9; ++k) S += sm[src + k * P_IN];
                    #pragma unroll
                    for (int j = 0; j < 8; ++j) {
                        sm[dst + j * P_IN] = S;
                        if (s == 0 && j == 4) keep = S;   // gy = y0 (edge if y0==0)
                        if (s == 2 && j == 3) keep = S;   // gy = y0+15 (edge if y0==176)
                        if (j < 7) S += sm[src + (j + 9) * P_IN] - sm[src + j * P_IN];
                    }
                    if (y0 == 0 && s == 0) {
                        #pragma unroll
                        for (int j = 0; j < 4; ++j) sm[dst + j * P_IN] = keep;
                    }
                    if (y0 == H_ - TY && s == 2) {
                        #pragma unroll
                        for (int j = 4; j < 8; ++j) sm[dst + j * P_IN] = keep;
                    }
                }
            }
            __syncthreads();
            ++zx;
        }

        // ---- Stage 2: mean z-window advance + centered products at slice zp ----
        {
            const long sb = (long)zp * HW_;
            if (zp == pLo) {
                int sl[9];
                #pragma unroll
                for (int k = 0; k < 9; ++k) sl[k] = iclampi(zp - 4 + k, 0, D_ - 1) % 10;
                for (int i = tid; i < IXW * IYH; i += 512) {
                    int y = i / IXW, x = i - y * IXW;
                    int a = y * P_IN + x;
                    float st = 0.f, sp = 0.f;
                    #pragma unroll
                    for (int k = 0; k < 9; ++k) {
                        st += sm[OFF_RXB + sl[k] * SZ_XB_SL + a];
                        sp += sm[OFF_RXB + (10 + sl[k]) * SZ_XB_SL + a];
                    }
                    sm[OFF_SZS + a] = st;
                    sm[OFF_SZS + SZ_XB_SL + a] = sp;
                    float mt = st * inv_win, mp = sp * inv_win;
                    int gx = iclampi(x0 - 4 + x, 0, W_ - 1);
                    int gy = iclampi(y0 - 4 + y, 0, H_ - 1);
                    long o = sb + (long)gy * W_ + gx;
                    float t = bT[o], p = bP[o];
                    float tc = t - mt, pc = p - mp;
                    sm[OFF_PROD + a]                = tc * pc;
                    sm[OFF_PROD + SZ_XB_SL + a]     = tc * tc;
                    sm[OFF_PROD + 2 * SZ_XB_SL + a] = pc * pc;
                }
            } else {
                const int sN = (min(zp + 4, D_ - 1)) % 10;
                const int sO = (max(zp - 5, 0)) % 10;
                for (int i = tid; i < IXW * IYH; i += 512) {
                    int y = i / IXW, x = i - y * IXW;
                    int a = y * P_IN + x;
                    float st = sm[OFF_SZS + a]
                             + sm[OFF_RXB + sN * SZ_XB_SL + a]
                             - sm[OFF_RXB + sO * SZ_XB_SL + a];
                    float sp = sm[OFF_SZS + SZ_XB_SL + a]
                             + sm[OFF_RXB + (10 + sN) * SZ_XB_SL + a]
                             - sm[OFF_RXB + (10 + sO) * SZ_XB_SL + a];
                    sm[OFF_SZS + a] = st;
                    sm[OFF_SZS + SZ_XB_SL + a] = sp;
                    float mt = st * inv_win, mp = sp * inv_win;
                    int gx = iclampi(x0 - 4 + x, 0, W_ - 1);
                    int gy = iclampi(y0 - 4 + y, 0, H_ - 1);
                    long o = sb + (long)gy * W_ + gx;
                    float t = bT[o], p = bP[o];
                    float tc = t - mt, pc = p - mp;
                    sm[OFF_PROD + a]                = tc * pc;
                    sm[OFF_PROD + SZ_XB_SL + a]     = tc * tc;
                    sm[OFF_PROD + 2 * SZ_XB_SL + a] = pc * pc;
                }
            }
        }
        __syncthreads();

        // ---- Stage 3a: x-box products (all centers valid): 24 rows x 4 segs x 3 fields ----
        if (tid < 288) {
            int f = tid % 3, w = tid / 3;
            int r = w / 4, s = w - r * 4;
            int src = OFF_PROD + f * SZ_XB_SL + r * P_IN + s * 8;
            int dst = OFF_TMP + f * TMP2_FS + r * P_OUT + s * 8;
            float S = 0.f;
            #pragma unroll
            for (int k = 0; k < 9; ++k) S += sm[src + k];
            #pragma unroll
            for (int j = 0; j < 8; ++j) {
                sm[dst + j] = S;
                if (j < 7) S += sm[src + j + 9] - sm[src + j];
            }
        }
        __syncthreads();
        // ---- Stage 3b: y-box products -> ring slot: 32 cols x 2 segs x 3 fields ----
        {
            const int slot = zp % 10;
            if (tid < 192) {
                int f = tid % 3, w = tid / 3;
                int c = w / 2, s = w - c * 2;
                int src = OFF_TMP + f * TMP2_FS + (s * 8) * P_OUT + c;
                int dst = OFF_RPXB + (f * 10 + slot) * SZ_PX_SL + (s * 8) * P_OUT + c;
                float S = 0.f;
                #pragma unroll
                for (int k = 0; k < 9; ++k) S += sm[src + k * P_OUT];
                #pragma unroll
                for (int j = 0; j < 8; ++j) {
                    sm[dst + j * P_OUT] = S;
                    if (j < 7) S += sm[src + (j + 9) * P_OUT] - sm[src + j * P_OUT];
                }
            }
        }
        __syncthreads();

        // ---- Emit ready output slices (thread owns output elem aOut) ----
        while (next_out < z0 + ZC && min(next_out + 4, D_ - 1) <= zp) {
            if (next_out == z0) {
                rSn = rSt = rSp = 0.f;
                #pragma unroll
                for (int k = 0; k < 9; ++k) {
                    int s = iclampi(next_out - 4 + k, 0, D_ - 1) % 10;
                    rSn += sm[OFF_RPXB + s * SZ_PX_SL + aOut];
                    rSt += sm[OFF_RPXB + (10 + s) * SZ_PX_SL + aOut];
                    rSp += sm[OFF_RPXB + (20 + s) * SZ_PX_SL + aOut];
                }
            } else {
                int sN = (min(next_out + 4, D_ - 1)) % 10;
                int sO = (max(next_out - 5, 0)) % 10;
                rSn += sm[OFF_RPXB + sN * SZ_PX_SL + aOut] - sm[OFF_RPXB + sO * SZ_PX_SL + aOut];
                rSt += sm[OFF_RPXB + (10 + sN) * SZ_PX_SL + aOut] - sm[OFF_RPXB + (10 + sO) * SZ_PX_SL + aOut];
                rSp += sm[OFF_RPXB + (20 + sN) * SZ_PX_SL + aOut] - sm[OFF_RPXB + (20 + sO) * SZ_PX_SL + aOut];
            }
            float cc = (rSn * rSn + eps) / (rSt * rSp + eps);
            acc += fminf(fmaxf(cc, 0.f), 1.f);
            ++next_out;
        }
    }

    // ---- Block reduction (deterministic fixed tree) ----
    __syncthreads();               // smem rings dead; reuse sm[0..15]
    float v = acc;
    #pragma unroll
    for (int o = 16; o; o >>= 1) v += __shfl_down_sync(0xffffffffu, v, o);
    if ((tid & 31) == 0) sm[tid >> 5] = v;
    __syncthreads();
    if (tid < 16) {
        float t = sm[tid];
        #pragma unroll
        for (int o = 8; o; o >>= 1) t += __shfl_down_sync(0xffffu, t, o);
        if (tid == 0) {
            int flat = blockIdx.x + GX * (blockIdx.y + GY * blockIdx.z);
            g_block[flat] = t;
        }
    }
}

// Finalize: sum block partials in double (deterministic) and write -mean.
__global__ void lncc_finalize_kernel(float* __restrict__ out)
{
    const int t = threadIdx.x; // 32 threads
    double s = 0.0;
    for (int i = t; i < NBLK; i += 32) s += (double)g_block[i];
    #pragma unroll
    for (int o = 16; o; o >>= 1) s += __shfl_down_sync(0xffffffffu, s, o);
    if (t == 0) out[0] = (float)(-s / (double)NTOT);
}

namespace {
struct KInit {
    KInit() {
        setenv("CUDA_MODULE_LOADING", "EAGER", 1);
        cudaFuncSetAttribute(lncc_fused_kernel,
                             cudaFuncAttributeMaxDynamicSharedMemorySize, SMEM_BYTES);
        cudaFuncAttributes a;
        cudaFuncGetAttributes(&a, lncc_fused_kernel);
        cudaFuncGetAttributes(&a, lncc_finalize_kernel);
    }
};
KInit kinit_;
}

extern "C" void kernel_launch(void* const* d_in, const int* in_sizes, int n_in,
                              void* d_out, int out_size)
{
    const float* y_true = (const float*)d_in[0];
    const float* y_pred = (const float*)d_in[1];
    float* out = (float*)d_out;
    (void)in_sizes; (void)n_in; (void)out_size;

    cudaFuncSetAttribute(lncc_fused_kernel,
                         cudaFuncAttributeMaxDynamicSharedMemorySize, SMEM_BYTES);
    dim3 grid(GX, GY, CZ * NB);
    lncc_fused_kernel<<<grid, 512, SMEM_BYTES>>>(y_true, y_pred);
    lncc_finalize_kernel<<<1, 32>>>(out);
}